// round 2
// baseline (speedup 1.0000x reference)
#include <cuda_runtime.h>
#include <math.h>

#define N3   16777216u           // 256^3
#define BROW 392                 // per-copy bin stride (floats), 3*129=387 used

__device__ float2 g_work[2u * N3];     // packed ref + i*pred spectrum scratch
__device__ double g_bins[800];         // [vol][label*3+comp]

// ---------------------------------------------------------------------------
// In-register 16-point radix-2 DIT FFT (forward).
// ---------------------------------------------------------------------------
__constant__ float TW16C[8] = { 1.0f,  0.9238795325112867f,  0.7071067811865476f,
                                0.3826834323650898f, 0.0f, -0.3826834323650898f,
                               -0.7071067811865476f, -0.9238795325112867f };
__constant__ float TW16S[8] = { 0.0f, -0.3826834323650898f, -0.7071067811865476f,
                               -0.9238795325112867f, -1.0f, -0.9238795325112867f,
                               -0.7071067811865476f, -0.3826834323650898f };

__device__ __forceinline__ void cswap(float2& a, float2& b) { float2 t = a; a = b; b = t; }

__device__ __forceinline__ void fft16(float2 v[16]) {
    cswap(v[1], v[8]);  cswap(v[2], v[4]);  cswap(v[3], v[12]);
    cswap(v[5], v[10]); cswap(v[7], v[14]); cswap(v[11], v[13]);
#pragma unroll
    for (int s = 1; s <= 4; s++) {
        const int m = 1 << s, hm = m >> 1;
#pragma unroll
        for (int k = 0; k < 16; k += m) {
#pragma unroll
            for (int j = 0; j < hm; j++) {
                const float wr = TW16C[j << (4 - s)];
                const float wi = TW16S[j << (4 - s)];
                float2 a = v[k + j], b = v[k + j + hm];
                float tr = b.x * wr - b.y * wi;
                float ti = b.x * wi + b.y * wr;
                v[k + j]      = make_float2(a.x + tr, a.y + ti);
                v[k + j + hm] = make_float2(a.x - tr, a.y - ti);
            }
        }
    }
}

// ---------------------------------------------------------------------------
// Pass 0: pack (ref + i*pred), FFT along W (contiguous).
// ---------------------------------------------------------------------------
__global__ void k_pass0(const float* __restrict__ ref, const float* __restrict__ pred) {
    __shared__ float2 sh[16 * 273];
    __shared__ float2 tw[256];

    const int tid = threadIdx.x;
    {
        float s, c;
        sincospif(-(float)tid / 128.0f, &s, &c);
        tw[tid] = make_float2(c, s);
    }
    const int bid  = blockIdx.x;
    const unsigned vol  = (unsigned)bid >> 12;
    const unsigned tile = (unsigned)bid & 4095u;
    const int l = tid >> 4;
    const int t = tid & 15;
    const unsigned base = vol * N3 + (tile * 16u + (unsigned)l) * 256u;

    float2 v[16];
#pragma unroll
    for (int n1 = 0; n1 < 16; n1++) {
        unsigned e = base + (unsigned)(n1 * 16 + t);
        v[n1] = make_float2(ref[e], pred[e]);
    }
    __syncthreads();

    fft16(v);
#pragma unroll
    for (int k1 = 0; k1 < 16; k1++) {
        float2 w = tw[t * k1];
        float xr = v[k1].x * w.x - v[k1].y * w.y;
        float xi = v[k1].x * w.y + v[k1].y * w.x;
        v[k1] = make_float2(xr, xi);
    }
    float2* lb = &sh[l * 273];
#pragma unroll
    for (int k1 = 0; k1 < 16; k1++) lb[t * 17 + k1] = v[k1];
    __syncthreads();
#pragma unroll
    for (int n2 = 0; n2 < 16; n2++) v[n2] = lb[n2 * 17 + t];
    fft16(v);
#pragma unroll
    for (int k2 = 0; k2 < 16; k2++)
        g_work[base + (unsigned)(k2 * 16 + t)] = v[k2];
}

// ---------------------------------------------------------------------------
// Templated strided FFT pass (used for H only now). Compile-time strides.
// ---------------------------------------------------------------------------
template<unsigned ES, unsigned OS>
__global__ void k_passS() {
    __shared__ float2 sh[16 * 273];
    __shared__ float2 tw[256];

    const int tid = threadIdx.x;
    {
        float s, c;
        sincospif(-(float)tid / 128.0f, &s, &c);
        tw[tid] = make_float2(c, s);
    }
    const int bid = blockIdx.x;
    const unsigned vol   = (unsigned)bid >> 12;
    const unsigned r     = (unsigned)bid & 4095u;
    const unsigned outer = r >> 4;
    const unsigned w0    = (r & 15u) * 16u;
    const int wl = tid & 15;
    const int t  = tid >> 4;
    const unsigned base = vol * N3 + outer * OS + w0 + (unsigned)wl;

    float2 v[16];
#pragma unroll
    for (int n1 = 0; n1 < 16; n1++)
        v[n1] = g_work[base + (unsigned)(n1 * 16 + t) * ES];
    __syncthreads();

    fft16(v);
#pragma unroll
    for (int k1 = 0; k1 < 16; k1++) {
        float2 w = tw[t * k1];
        float xr = v[k1].x * w.x - v[k1].y * w.y;
        float xi = v[k1].x * w.y + v[k1].y * w.x;
        v[k1] = make_float2(xr, xi);
    }
    float2* lb = &sh[wl * 273];
#pragma unroll
    for (int k1 = 0; k1 < 16; k1++) lb[t * 17 + k1] = v[k1];
    __syncthreads();
#pragma unroll
    for (int n2 = 0; n2 < 16; n2++) v[n2] = lb[n2 * 17 + t];
    fft16(v);
#pragma unroll
    for (int k2 = 0; k2 < 16; k2++)
        g_work[base + (unsigned)(k2 * 16 + t) * ES] = v[k2];
}

// ---------------------------------------------------------------------------
// Fused D-pass + shell reduction. Each block FFTs (along D) 16 primary lines
// A=(hA, w=16c+j) and their 16 mirror lines B=(hB, w=(256-16c-j)&255), keeps
// both in shared, then bins every (k,-k) pair in-block. No global Z write.
//
// Pair contribution (unordered pair counted once, labels symmetric):
//   S0 += |a|^2 + |b|^2 ; S1 += 2*Re(a*b) ; S2 += 2*Im(a*b)
// Self element (k == -k): S0 += |b|^2 ; S1 += Re(b^2) ; S2 += Im(b^2)
// ---------------------------------------------------------------------------
extern __shared__ float2 dynsh[];

__device__ __forceinline__ void binPair(float* bins, int l, float2 a, float2 b) {
    atomicAdd(&bins[l * 3 + 0], a.x * a.x + a.y * a.y + b.x * b.x + b.y * b.y);
    atomicAdd(&bins[l * 3 + 1], 2.0f * (a.x * b.x - a.y * b.y));
    atomicAdd(&bins[l * 3 + 2], 2.0f * (a.x * b.y + a.y * b.x));
}
__device__ __forceinline__ void binSelf(float* bins, int l, float2 b) {
    atomicAdd(&bins[l * 3 + 0], b.x * b.x + b.y * b.y);
    atomicAdd(&bins[l * 3 + 1], b.x * b.x - b.y * b.y);
    atomicAdd(&bins[l * 3 + 2], 2.0f * b.x * b.y);
}
__device__ __forceinline__ int slbl(int c2) {
    return min((int)__fsqrt_rn((float)c2), 128);
}

__global__ void k_fusedD() {
    float2* bufA = dynsh;                 // 16*273
    float2* bufB = dynsh + 4368;          // 16*273
    float2* tw   = dynsh + 8736;          // 256
    float*  sbf  = (float*)(dynsh + 8992);// 8 copies * BROW floats

    const int tid = threadIdx.x;
    {
        float s, c;
        sincospif(-(float)tid / 128.0f, &s, &c);
        tw[tid] = make_float2(c, s);
    }
    for (int i = tid; i < 8 * BROW; i += 256) sbf[i] = 0.0f;

    const unsigned bid = blockIdx.x;
    const unsigned vol = bid >> 11;
    const unsigned r   = bid & 2047u;
    const unsigned volBase = vol * N3;

    unsigned hA, c;
    bool special = false;
    if (r < 2032u) {                       // case 1: h in 1..127, c in 0..15
        hA = 1u + (r >> 4);
        c  = r & 15u;
    } else {                               // case 2: h in {0,128}, c in 0..7
        unsigned idx = r - 2032u;
        hA = (idx < 8u) ? 0u : 128u;
        c  = idx & 7u;
        special = (c == 0u);
    }
    const unsigned hB = (256u - hA) & 255u;   // == hA for case 2

    const int wl = tid & 15;
    const int t  = tid >> 4;

    const unsigned wA = 16u * c + (unsigned)wl;
    unsigned wB = (256u - 16u * c - (unsigned)wl) & 255u;
    if (special && wl == 0) wB = 128u;     // replace duplicate w=0 with w=128

    __syncthreads();                       // tw + bins ready

    float2 v[16];
    // ---- phase A: FFT primary lines along D ----
    {
        const unsigned base = volBase + hA * 256u + wA;
#pragma unroll
        for (int n1 = 0; n1 < 16; n1++)
            v[n1] = g_work[base + (unsigned)(n1 * 16 + t) * 65536u];
        fft16(v);
#pragma unroll
        for (int k1 = 0; k1 < 16; k1++) {
            float2 w = tw[t * k1];
            float xr = v[k1].x * w.x - v[k1].y * w.y;
            float xi = v[k1].x * w.y + v[k1].y * w.x;
            v[k1] = make_float2(xr, xi);
        }
        float2* lb = &bufA[wl * 273];
#pragma unroll
        for (int k1 = 0; k1 < 16; k1++) lb[t * 17 + k1] = v[k1];
        __syncthreads();
#pragma unroll
        for (int n2 = 0; n2 < 16; n2++) v[n2] = lb[n2 * 17 + t];
        __syncthreads();                   // all transpose reads done
        fft16(v);
#pragma unroll
        for (int k2 = 0; k2 < 16; k2++) lb[k2 * 16 + t] = v[k2];   // Z_A[d]
    }
    // ---- phase B: FFT mirror lines along D ----
    {
        const unsigned base = volBase + hB * 256u + wB;
#pragma unroll
        for (int n1 = 0; n1 < 16; n1++)
            v[n1] = g_work[base + (unsigned)(n1 * 16 + t) * 65536u];
        fft16(v);
#pragma unroll
        for (int k1 = 0; k1 < 16; k1++) {
            float2 w = tw[t * k1];
            float xr = v[k1].x * w.x - v[k1].y * w.y;
            float xi = v[k1].x * w.y + v[k1].y * w.x;
            v[k1] = make_float2(xr, xi);
        }
        float2* lb = &bufB[wl * 273];
#pragma unroll
        for (int k1 = 0; k1 < 16; k1++) lb[t * 17 + k1] = v[k1];
        __syncthreads();
#pragma unroll
        for (int n2 = 0; n2 < 16; n2++) v[n2] = lb[n2 * 17 + t];
        __syncthreads();
        fft16(v);
#pragma unroll
        for (int k2 = 0; k2 < 16; k2++) lb[k2 * 16 + t] = v[k2];   // Z_B[d]
    }
    __syncthreads();                       // bufA & bufB fully populated

    // ---- binning ----
    float* bins = sbf + ((tid >> 5) & 7) * BROW;
    const int shh = (hB < 128u) ? (int)hB : (int)hB - 256;
    const int sww = (wB < 128u) ? (int)wB : (int)wB - 256;
    const int c2hw = shh * shh + sww * sww;

    if (!(special && wl == 0)) {
        // normal pair binning: b = Z_B(d), a = Z_A(-d) from bufA row wl
#pragma unroll
        for (int k2 = 0; k2 < 16; k2++) {
            const int d  = k2 * 16 + t;
            const int dm = (256 - d) & 255;
            const float2 b = v[k2];
            const float2 a = bufA[wl * 273 + dm];
            const int sd = (d < 128) ? d : d - 256;
            binPair(bins, slbl(c2hw + sd * sd), a, b);
        }
    } else {
        // self-line w=128 (h0 plane): pair within own line across d
#pragma unroll
        for (int k2 = 0; k2 < 16; k2++) {
            const int d = k2 * 16 + t;
            const float2 b = v[k2];
            if (d == 0 || d == 128) {
                const int sd = (d < 128) ? d : d - 256;
                binSelf(bins, slbl(c2hw + sd * sd), b);
            } else if (d < 128) {
                const float2 a = bufB[0 * 273 + (256 - d)];
                binPair(bins, slbl(c2hw + d * d), a, b);
            }
        }
    }
    if (special && wl == 1) {
        // extra: self-line w=0 (h0 plane) from bufA row 0
        const int c2h0 = shh * shh;        // w=0
#pragma unroll
        for (int k2 = 0; k2 < 16; k2++) {
            const int d = k2 * 16 + t;
            const float2 b = bufA[0 * 273 + d];
            if (d == 0 || d == 128) {
                const int sd = (d < 128) ? d : d - 256;
                binSelf(bins, slbl(c2h0 + sd * sd), b);
            } else if (d < 128) {
                const float2 a = bufA[0 * 273 + (256 - d)];
                binPair(bins, slbl(c2h0 + d * d), a, b);
            }
        }
    }
    __syncthreads();

    for (int i = tid; i < 387; i += 256) {
        float s = 0.0f;
#pragma unroll
        for (int cpy = 0; cpy < 8; cpy++) s += sbf[cpy * BROW + i];
        atomicAdd(&g_bins[vol * 400u + (unsigned)i], (double)s);
    }
}

// ---------------------------------------------------------------------------
__global__ void k_final(float* out) {
    __shared__ double red[256];
    const int tid = threadIdx.x;
    const unsigned vol = (unsigned)tid >> 7;
    const unsigned bin = (unsigned)tid & 127u;
    const double S0 = g_bins[vol * 400u + bin * 3u + 0u];
    const double S1 = g_bins[vol * 400u + bin * 3u + 1u];
    const double S2 = g_bins[vol * 400u + bin * 3u + 2u];
    const double num = 0.5 * S2;
    const double d1 = 0.5 * (S0 + S1);
    const double d2 = 0.5 * (S0 - S1);
    const double f2 = (num * num) / (d1 * d2 + 1e-8);
    red[tid] = f2;
    __syncthreads();
    for (int s = 128; s > 0; s >>= 1) {
        if (tid < s) red[tid] += red[tid + s];
        __syncthreads();
    }
    if (tid == 0) out[0] = (float)(1.0 - red[0] / 256.0);
}

__global__ void k_zero() {
    int i = blockIdx.x * blockDim.x + threadIdx.x;
    if (i < 800) g_bins[i] = 0.0;
}

// ---------------------------------------------------------------------------
extern "C" void kernel_launch(void* const* d_in, const int* in_sizes, int n_in,
                              void* d_out, int out_size) {
    const float* ref  = (const float*)d_in[0];
    const float* pred = (const float*)d_in[1];
    float* out = (float*)d_out;

    static const int FUSED_SMEM = (8992 + 1568) * 8;   // 84480 B
    cudaFuncSetAttribute(k_fusedD, cudaFuncAttributeMaxDynamicSharedMemorySize,
                         FUSED_SMEM);

    k_zero<<<4, 256>>>();
    k_pass0<<<8192, 256>>>(ref, pred);                 // pack + FFT along W
    k_passS<256u, 65536u><<<8192, 256>>>();            // FFT along H
    k_fusedD<<<4096, 256, FUSED_SMEM>>>();             // FFT along D + binning
    k_final<<<1, 256>>>(out);                          // scalar loss
}

// round 3
// speedup vs baseline: 1.3303x; 1.3303x over previous
#include <cuda_runtime.h>
#include <math.h>

#define N3   16777216u           // 256^3
#define SSTR 257                 // smem row stride (float2), 256 used + pad
#define BROW 392                 // per-copy bin stride (floats), 3*129=387 used
#define NCPY 4

__device__ float2 g_work[2u * N3];     // packed ref + i*pred spectrum scratch
__device__ double g_bins[800];         // [vol][label*3+comp]

// ---------------------------------------------------------------------------
// In-register 16-point radix-2 DIT FFT (forward).
// ---------------------------------------------------------------------------
__constant__ float TW16C[8] = { 1.0f,  0.9238795325112867f,  0.7071067811865476f,
                                0.3826834323650898f, 0.0f, -0.3826834323650898f,
                               -0.7071067811865476f, -0.9238795325112867f };
__constant__ float TW16S[8] = { 0.0f, -0.3826834323650898f, -0.7071067811865476f,
                               -0.9238795325112867f, -1.0f, -0.9238795325112867f,
                               -0.7071067811865476f, -0.3826834323650898f };

__device__ __forceinline__ void cswap(float2& a, float2& b) { float2 t = a; a = b; b = t; }

__device__ __forceinline__ void fft16(float2 v[16]) {
    cswap(v[1], v[8]);  cswap(v[2], v[4]);  cswap(v[3], v[12]);
    cswap(v[5], v[10]); cswap(v[7], v[14]); cswap(v[11], v[13]);
#pragma unroll
    for (int s = 1; s <= 4; s++) {
        const int m = 1 << s, hm = m >> 1;
#pragma unroll
        for (int k = 0; k < 16; k += m) {
#pragma unroll
            for (int j = 0; j < hm; j++) {
                const float wr = TW16C[j << (4 - s)];
                const float wi = TW16S[j << (4 - s)];
                float2 a = v[k + j], b = v[k + j + hm];
                float tr = b.x * wr - b.y * wi;
                float ti = b.x * wi + b.y * wr;
                v[k + j]      = make_float2(a.x + tr, a.y + ti);
                v[k + j + hm] = make_float2(a.x - tr, a.y - ti);
            }
        }
    }
}

// Twiddle by W_256^{t*k1} using a register recurrence (no smem table).
__device__ __forceinline__ void twmul(float2 v[16], int t) {
    float bs, bc;
    sincospif(-(float)t / 128.0f, &bs, &bc);   // exp(-2*pi*i*t/256)
    float wr = bc, wi = bs;
#pragma unroll
    for (int k1 = 1; k1 < 16; k1++) {
        float xr = v[k1].x * wr - v[k1].y * wi;
        float xi = v[k1].x * wi + v[k1].y * wr;
        v[k1] = make_float2(xr, xi);
        float nr = wr * bc - wi * bs;
        float ni = wr * bs + wi * bc;
        wr = nr; wi = ni;
    }
}

// ---------------------------------------------------------------------------
// Pass 0: pack (ref + i*pred), FFT along W (contiguous).
// ---------------------------------------------------------------------------
__global__ void __launch_bounds__(256, 3)
k_pass0(const float* __restrict__ ref, const float* __restrict__ pred) {
    __shared__ float2 sh[16 * SSTR];

    const int tid = threadIdx.x;
    const int bid = blockIdx.x;
    const unsigned vol  = (unsigned)bid >> 12;
    const unsigned tile = (unsigned)bid & 4095u;
    const int l = tid >> 4;
    const int t = tid & 15;
    const unsigned base = vol * N3 + (tile * 16u + (unsigned)l) * 256u;

    float2 v[16];
#pragma unroll
    for (int n1 = 0; n1 < 16; n1++) {
        unsigned e = base + (unsigned)(n1 * 16 + t);
        v[n1] = make_float2(ref[e], pred[e]);
    }
    fft16(v);
    twmul(v, t);
    float2* lb = &sh[l * SSTR];
#pragma unroll
    for (int k1 = 0; k1 < 16; k1++) lb[t * 16 + k1] = v[k1];
    __syncthreads();
#pragma unroll
    for (int n2 = 0; n2 < 16; n2++) v[n2] = lb[n2 * 16 + t];
    fft16(v);
#pragma unroll
    for (int k2 = 0; k2 < 16; k2++)
        g_work[base + (unsigned)(k2 * 16 + t)] = v[k2];
}

// ---------------------------------------------------------------------------
// Templated strided FFT pass (H).
// ---------------------------------------------------------------------------
template<unsigned ES, unsigned OS>
__global__ void __launch_bounds__(256, 3) k_passS() {
    __shared__ float2 sh[16 * SSTR];

    const int tid = threadIdx.x;
    const int bid = blockIdx.x;
    const unsigned vol   = (unsigned)bid >> 12;
    const unsigned r     = (unsigned)bid & 4095u;
    const unsigned outer = r >> 4;
    const unsigned w0    = (r & 15u) * 16u;
    const int wl = tid & 15;
    const int t  = tid >> 4;
    const unsigned base = vol * N3 + outer * OS + w0 + (unsigned)wl;

    float2 v[16];
#pragma unroll
    for (int n1 = 0; n1 < 16; n1++)
        v[n1] = g_work[base + (unsigned)(n1 * 16 + t) * ES];
    fft16(v);
    twmul(v, t);
    float2* lb = &sh[wl * SSTR];
#pragma unroll
    for (int k1 = 0; k1 < 16; k1++) lb[t * 16 + k1] = v[k1];
    __syncthreads();
#pragma unroll
    for (int n2 = 0; n2 < 16; n2++) v[n2] = lb[n2 * 16 + t];
    fft16(v);
#pragma unroll
    for (int k2 = 0; k2 < 16; k2++)
        g_work[base + (unsigned)(k2 * 16 + t) * ES] = v[k2];
}

// ---------------------------------------------------------------------------
// Fused D-pass + shell reduction (validated logic from R2, restructured).
// ---------------------------------------------------------------------------
extern __shared__ float2 dynsh[];

__device__ __forceinline__ void binPair(float* bins, int l, float2 a, float2 b) {
    atomicAdd(&bins[l * 3 + 0], a.x * a.x + a.y * a.y + b.x * b.x + b.y * b.y);
    atomicAdd(&bins[l * 3 + 1], 2.0f * (a.x * b.x - a.y * b.y));
    atomicAdd(&bins[l * 3 + 2], 2.0f * (a.x * b.y + a.y * b.x));
}
__device__ __forceinline__ void binSelf(float* bins, int l, float2 b) {
    atomicAdd(&bins[l * 3 + 0], b.x * b.x + b.y * b.y);
    atomicAdd(&bins[l * 3 + 1], b.x * b.x - b.y * b.y);
    atomicAdd(&bins[l * 3 + 2], 2.0f * b.x * b.y);
}
__device__ __forceinline__ int slbl(int c2) {
    return min((int)__fsqrt_rn((float)c2), 128);
}

__global__ void __launch_bounds__(256, 3) k_fusedD() {
    float2* bufA = dynsh;                     // 16*SSTR float2
    float2* bufB = dynsh + 16 * SSTR;         // 16*SSTR float2
    float*  sbf  = (float*)(dynsh + 32 * SSTR); // NCPY * BROW floats

    const int tid = threadIdx.x;
    for (int i = tid; i < NCPY * BROW; i += 256) sbf[i] = 0.0f;

    const unsigned bid = blockIdx.x;
    const unsigned vol = bid >> 11;
    const unsigned r   = bid & 2047u;
    const unsigned volBase = vol * N3;

    unsigned hA, c;
    bool special = false;
    if (r < 2032u) {                       // h in 1..127, c in 0..15
        hA = 1u + (r >> 4);
        c  = r & 15u;
    } else {                               // h in {0,128}, c in 0..7
        unsigned idx = r - 2032u;
        hA = (idx < 8u) ? 0u : 128u;
        c  = idx & 7u;
        special = (c == 0u);
    }
    const unsigned hB = (256u - hA) & 255u;

    const int wl = tid & 15;
    const int t  = tid >> 4;

    const unsigned wA = 16u * c + (unsigned)wl;
    unsigned wB = (256u - 16u * c - (unsigned)wl) & 255u;
    if (special && wl == 0) wB = 128u;

    float2 v[16];
    // ---- phase A ----
    {
        const unsigned base = volBase + hA * 256u + wA;
#pragma unroll
        for (int n1 = 0; n1 < 16; n1++)
            v[n1] = g_work[base + (unsigned)(n1 * 16 + t) * 65536u];
        fft16(v);
        twmul(v, t);
        float2* lb = &bufA[wl * SSTR];
#pragma unroll
        for (int k1 = 0; k1 < 16; k1++) lb[t * 16 + k1] = v[k1];
        __syncthreads();
#pragma unroll
        for (int n2 = 0; n2 < 16; n2++) v[n2] = lb[n2 * 16 + t];
        __syncthreads();                   // reads done before overwrite
        fft16(v);
#pragma unroll
        for (int k2 = 0; k2 < 16; k2++) lb[k2 * 16 + t] = v[k2];   // Z_A[d]
    }
    // ---- phase B ----
    {
        const unsigned base = volBase + hB * 256u + wB;
#pragma unroll
        for (int n1 = 0; n1 < 16; n1++)
            v[n1] = g_work[base + (unsigned)(n1 * 16 + t) * 65536u];
        fft16(v);
        twmul(v, t);
        float2* lb = &bufB[wl * SSTR];
#pragma unroll
        for (int k1 = 0; k1 < 16; k1++) lb[t * 16 + k1] = v[k1];
        __syncthreads();                   // also makes bufA final visible
#pragma unroll
        for (int n2 = 0; n2 < 16; n2++) v[n2] = lb[n2 * 16 + t];
        fft16(v);
        if (special) {                     // only special blocks need Z_B in smem
            __syncthreads();
#pragma unroll
            for (int k2 = 0; k2 < 16; k2++) lb[k2 * 16 + t] = v[k2];
        }
    }
    __syncthreads();

    // ---- binning ----
    float* bins = sbf + (tid & 3) * BROW;
    const int shh = (hB < 128u) ? (int)hB : (int)hB - 256;
    const int sww = (wB < 128u) ? (int)wB : (int)wB - 256;
    const int c2hw = shh * shh + sww * sww;

    if (!(special && wl == 0)) {
#pragma unroll
        for (int k2 = 0; k2 < 16; k2++) {
            const int d  = k2 * 16 + t;
            const int dm = (256 - d) & 255;
            const float2 b = v[k2];
            const float2 a = bufA[wl * SSTR + dm];
            const int sd = (d < 128) ? d : d - 256;
            binPair(bins, slbl(c2hw + sd * sd), a, b);
        }
    } else {
#pragma unroll
        for (int k2 = 0; k2 < 16; k2++) {
            const int d = k2 * 16 + t;
            const float2 b = v[k2];
            if (d == 0 || d == 128) {
                const int sd = (d < 128) ? d : d - 256;
                binSelf(bins, slbl(c2hw + sd * sd), b);
            } else if (d < 128) {
                const float2 a = bufB[0 * SSTR + (256 - d)];
                binPair(bins, slbl(c2hw + d * d), a, b);
            }
        }
    }
    if (special && wl == 1) {
        const int c2h0 = shh * shh;        // w = 0 line
#pragma unroll
        for (int k2 = 0; k2 < 16; k2++) {
            const int d = k2 * 16 + t;
            const float2 b = bufA[0 * SSTR + d];
            if (d == 0 || d == 128) {
                const int sd = (d < 128) ? d : d - 256;
                binSelf(bins, slbl(c2h0 + sd * sd), b);
            } else if (d < 128) {
                const float2 a = bufA[0 * SSTR + (256 - d)];
                binPair(bins, slbl(c2h0 + d * d), a, b);
            }
        }
    }
    __syncthreads();

    for (int i = tid; i < 387; i += 256) {
        float s = 0.0f;
#pragma unroll
        for (int cpy = 0; cpy < NCPY; cpy++) s += sbf[cpy * BROW + i];
        atomicAdd(&g_bins[vol * 400u + (unsigned)i], (double)s);
    }
}

// ---------------------------------------------------------------------------
__global__ void k_final(float* out) {
    __shared__ double red[256];
    const int tid = threadIdx.x;
    const unsigned vol = (unsigned)tid >> 7;
    const unsigned bin = (unsigned)tid & 127u;
    const double S0 = g_bins[vol * 400u + bin * 3u + 0u];
    const double S1 = g_bins[vol * 400u + bin * 3u + 1u];
    const double S2 = g_bins[vol * 400u + bin * 3u + 2u];
    const double num = 0.5 * S2;
    const double d1 = 0.5 * (S0 + S1);
    const double d2 = 0.5 * (S0 - S1);
    const double f2 = (num * num) / (d1 * d2 + 1e-8);
    red[tid] = f2;
    __syncthreads();
    for (int s = 128; s > 0; s >>= 1) {
        if (tid < s) red[tid] += red[tid + s];
        __syncthreads();
    }
    if (tid == 0) out[0] = (float)(1.0 - red[0] / 256.0);
}

__global__ void k_zero() {
    int i = blockIdx.x * blockDim.x + threadIdx.x;
    if (i < 800) g_bins[i] = 0.0;
}

// ---------------------------------------------------------------------------
extern "C" void kernel_launch(void* const* d_in, const int* in_sizes, int n_in,
                              void* d_out, int out_size) {
    const float* ref  = (const float*)d_in[0];
    const float* pred = (const float*)d_in[1];
    float* out = (float*)d_out;

    const int FUSED_SMEM = 32 * SSTR * 8 + NCPY * BROW * 4;  // 72064 B
    cudaFuncSetAttribute(k_fusedD, cudaFuncAttributeMaxDynamicSharedMemorySize,
                         FUSED_SMEM);

    k_zero<<<4, 256>>>();
    k_pass0<<<8192, 256>>>(ref, pred);                 // pack + FFT along W
    k_passS<256u, 65536u><<<8192, 256>>>();            // FFT along H
    k_fusedD<<<4096, 256, FUSED_SMEM>>>();             // FFT along D + binning
    k_final<<<1, 256>>>(out);                          // scalar loss
}